// round 3
// baseline (speedup 1.0000x reference)
#include <cuda_runtime.h>
#include <math.h>

#define NV   262144
#define NE   786432
#define CIMG 256
#define HID  128
#define HW   64
#define NPIX (HW*HW)
#define DIN  (HID+3)

// Scratch (allowed: __device__ globals, no allocation)
__device__ float g_P[NPIX * HID];                  // 2 MB: per-pixel projected feats
__device__ float g_bufA[(size_t)NV * HID];         // 134 MB
__device__ float g_bufB[(size_t)NV * HID];         // 134 MB
__device__ float g_bufZ[(size_t)NV * HID];         // 134 MB

// ---------------- helpers ----------------
__device__ __forceinline__ unsigned long long bcast2(float a) {
    unsigned long long r;
    asm("mov.b64 %0, {%1, %1};" : "=l"(r) : "f"(a));
    return r;
}
__device__ __forceinline__ void fma2(unsigned long long &c, unsigned long long a, unsigned long long b) {
    asm("fma.rn.f32x2 %0, %1, %2, %0;" : "+l"(c) : "l"(a), "l"(b));
}
__device__ __forceinline__ void red4(float* p, float4 v) {
    asm volatile("red.global.add.v4.f32 [%0], {%1, %2, %3, %4};"
                 :: "l"(p), "f"(v.x), "f"(v.y), "f"(v.z), "f"(v.w) : "memory");
}

// ---------------- kernel 1: P[p][j] = sum_c x[c][p] * bw[c][j] ----------------
__global__ void pixel_proj_kernel(const float* __restrict__ x, const float* __restrict__ bw) {
    int j = threadIdx.x;                       // 0..127
    int p = blockIdx.x * blockDim.y + threadIdx.y;
    const float* xp = x + p;
    const float* wp = bw + j;
    float acc = 0.f;
    #pragma unroll 8
    for (int c = 0; c < CIMG; c++)
        acc = fmaf(xp[(size_t)c * NPIX], wp[(size_t)c * HID], acc);
    g_P[(size_t)p * HID + j] = acc;
}

// ---------------- kernel 2: per-vertex bilinear blend of P + bias + relu -> g_bufA ----------------
__global__ void sample_kernel(const float* __restrict__ verts, const float* __restrict__ bb) {
    int w    = (blockIdx.x * blockDim.x + threadIdx.x) >> 5;
    int lane = threadIdx.x & 31;
    if (w >= NV) return;
    float vx = verts[3 * w], vy = verts[3 * w + 1];
    float px = (vx + 1.f) * 0.5f * (HW - 1);
    float py = (vy + 1.f) * 0.5f * (HW - 1);
    float fx = floorf(px), fy = floorf(py);
    float wx = px - fx,    wy = py - fy;
    int x0 = (int)fx; x0 = min(max(x0, 0), HW - 1); int x1 = min(x0 + 1, HW - 1);
    int y0 = (int)fy; y0 = min(max(y0, 0), HW - 1); int y1 = min(y0 + 1, HW - 1);

    const float* P00 = g_P + (size_t)(y0 * HW + x0) * HID;
    const float* P01 = g_P + (size_t)(y0 * HW + x1) * HID;
    const float* P10 = g_P + (size_t)(y1 * HW + x0) * HID;
    const float* P11 = g_P + (size_t)(y1 * HW + x1) * HID;

    int j = lane * 4;
    float4 a = *(const float4*)(P00 + j);
    float4 b = *(const float4*)(P01 + j);
    float4 c = *(const float4*)(P10 + j);
    float4 d = *(const float4*)(P11 + j);
    float4 bias4 = *(const float4*)(bb + j);

    float4 h;
    // match reference: top = v00*(1-wx)+v01*wx ; out = top*(1-wy)+bot*wy
    h.x = (a.x * (1.f - wx) + b.x * wx) * (1.f - wy) + (c.x * (1.f - wx) + d.x * wx) * wy + bias4.x;
    h.y = (a.y * (1.f - wx) + b.y * wx) * (1.f - wy) + (c.y * (1.f - wx) + d.y * wx) * wy + bias4.y;
    h.z = (a.z * (1.f - wx) + b.z * wx) * (1.f - wy) + (c.z * (1.f - wx) + d.z * wx) * wy + bias4.z;
    h.w = (a.w * (1.f - wx) + b.w * wx) * (1.f - wy) + (c.w * (1.f - wx) + d.w * wx) * wy + bias4.w;
    h.x = fmaxf(h.x, 0.f); h.y = fmaxf(h.y, 0.f); h.z = fmaxf(h.z, 0.f); h.w = fmaxf(h.w, 0.f);
    *(float4*)(g_bufA + (size_t)w * HID + j) = h;
}

// ---------------- kernel 3: Out[V,128] = relu(A[V,128]) @ W[0:128] + verts @ W[128:131] + bias ----------------
// (relu on load is idempotent for the already-activated bottleneck output)
__global__ void __launch_bounds__(256, 2)
gemm131_kernel(const float* __restrict__ A, const float* __restrict__ verts,
               const float* __restrict__ Wm, const float* __restrict__ bias,
               float* __restrict__ Out) {
    __shared__ __align__(16) unsigned long long Asd[8][132];  // A values pre-duplicated (f32x2 broadcast)
    __shared__ __align__(16) float Bs[8][128];

    const int tid = threadIdx.x;
    const int tr  = tid >> 4;       // 0..15  -> rows tr*8..+7
    const int tc  = tid & 15;       // 0..15  -> cols tc*8..+7
    const int row0 = blockIdx.x * 128;

    unsigned long long acc[8][4];
    #pragma unroll
    for (int i = 0; i < 8; i++)
        #pragma unroll
        for (int jj = 0; jj < 4; jj++) acc[i][jj] = 0ull;

    const int mA   = tid >> 1;          // 0..127
    const int offA = (tid & 1) * 4;     // 0 or 4
    const float* aptr = A + (size_t)(row0 + mA) * HID + offA;
    const int kB   = tid >> 5;          // 0..7
    const int colB = (tid & 31) * 4;    // 0..124

    // prefetch first tile
    float4 av = *(const float4*)(aptr);
    float4 bv = *(const float4*)(Wm + (size_t)kB * HID + colB);
    av.x = fmaxf(av.x, 0.f); av.y = fmaxf(av.y, 0.f); av.z = fmaxf(av.z, 0.f); av.w = fmaxf(av.w, 0.f);

    #pragma unroll 1
    for (int kk = 0; kk < HID; kk += 8) {
        Asd[offA + 0][mA] = bcast2(av.x);
        Asd[offA + 1][mA] = bcast2(av.y);
        Asd[offA + 2][mA] = bcast2(av.z);
        Asd[offA + 3][mA] = bcast2(av.w);
        *(float4*)&Bs[kB][colB] = bv;
        __syncthreads();

        float4 avn, bvn;
        bool more = (kk + 8) < HID;
        if (more) {
            avn = *(const float4*)(aptr + kk + 8);
            bvn = *(const float4*)(Wm + (size_t)(kk + 8 + kB) * HID + colB);
            avn.x = fmaxf(avn.x, 0.f); avn.y = fmaxf(avn.y, 0.f);
            avn.z = fmaxf(avn.z, 0.f); avn.w = fmaxf(avn.w, 0.f);
        }

        #pragma unroll
        for (int k = 0; k < 8; k++) {
            unsigned long long ap[8];
            #pragma unroll
            for (int i = 0; i < 8; i++) ap[i] = Asd[k][tr * 8 + i];
            ulonglong2 b01 = *(const ulonglong2*)&Bs[k][tc * 8];
            ulonglong2 b23 = *(const ulonglong2*)&Bs[k][tc * 8 + 4];
            #pragma unroll
            for (int i = 0; i < 8; i++) {
                fma2(acc[i][0], ap[i], b01.x);
                fma2(acc[i][1], ap[i], b01.y);
                fma2(acc[i][2], ap[i], b23.x);
                fma2(acc[i][3], ap[i], b23.y);
            }
        }
        __syncthreads();
        if (more) { av = avn; bv = bvn; }
    }

    // epilogue: rank-3 verts update + bias, store
    const int mycol = tc * 8;
    float wt0[8], wt1[8], wt2[8], bb8[8];
    #pragma unroll
    for (int jj = 0; jj < 8; jj++) {
        wt0[jj] = Wm[(size_t)(HID + 0) * HID + mycol + jj];
        wt1[jj] = Wm[(size_t)(HID + 1) * HID + mycol + jj];
        wt2[jj] = Wm[(size_t)(HID + 2) * HID + mycol + jj];
        bb8[jj] = bias[mycol + jj];
    }
    #pragma unroll
    for (int i = 0; i < 8; i++) {
        int r = row0 + tr * 8 + i;
        float vx = verts[3 * r], vy = verts[3 * r + 1], vz = verts[3 * r + 2];
        float o[8];
        #pragma unroll
        for (int jj = 0; jj < 4; jj++) {
            float2 cc = *reinterpret_cast<float2*>(&acc[i][jj]);
            o[2 * jj] = cc.x; o[2 * jj + 1] = cc.y;
        }
        #pragma unroll
        for (int jj = 0; jj < 8; jj++)
            o[jj] += vx * wt0[jj] + vy * wt1[jj] + vz * wt2[jj] + bb8[jj];
        float4* outp = (float4*)(Out + (size_t)r * HID + mycol);
        outp[0] = make_float4(o[0], o[1], o[2], o[3]);
        outp[1] = make_float4(o[4], o[5], o[6], o[7]);
    }
}

// ---------------- kernel 4: edge scatter  Y[e0] += Z[e1]; Y[e1] += Z[e0] ----------------
__global__ void scatter_kernel(const int* __restrict__ edges,
                               const float* __restrict__ Z, float* __restrict__ Y) {
    int t = blockIdx.x * blockDim.x + threadIdx.x;
    int e = t >> 5;
    int lane = t & 31;
    if (e >= NE) return;
    int a = edges[2 * e], b = edges[2 * e + 1];
    int j = lane * 4;
    float4 zb = *(const float4*)(Z + (size_t)b * HID + j);
    red4(Y + (size_t)a * HID + j, zb);
    float4 za = *(const float4*)(Z + (size_t)a * HID + j);
    red4(Y + (size_t)b * HID + j, za);
}

// ---------------- kernel 5: final head ----------------
// feats = relu(buf); out[0:3V) = verts + tanh(concat(feats,verts) @ ow + ob); out[3V:) = feats
__global__ void final_kernel(const float* __restrict__ buf, const float* __restrict__ verts,
                             const float* __restrict__ ow, const float* __restrict__ ob,
                             float* __restrict__ out) {
    __shared__ float sw[DIN * 3];
    for (int i = threadIdx.x; i < DIN * 3; i += blockDim.x) sw[i] = ow[i];
    __syncthreads();

    int w    = (blockIdx.x * blockDim.x + threadIdx.x) >> 5;
    int lane = threadIdx.x & 31;
    if (w >= NV) return;
    int j = lane * 4;
    float4 f = *(const float4*)(buf + (size_t)w * HID + j);
    f.x = fmaxf(f.x, 0.f); f.y = fmaxf(f.y, 0.f); f.z = fmaxf(f.z, 0.f); f.w = fmaxf(f.w, 0.f);
    *(float4*)(out + (size_t)3 * NV + (size_t)w * HID + j) = f;

    float a0 = f.x * sw[(j + 0) * 3 + 0] + f.y * sw[(j + 1) * 3 + 0] + f.z * sw[(j + 2) * 3 + 0] + f.w * sw[(j + 3) * 3 + 0];
    float a1 = f.x * sw[(j + 0) * 3 + 1] + f.y * sw[(j + 1) * 3 + 1] + f.z * sw[(j + 2) * 3 + 1] + f.w * sw[(j + 3) * 3 + 1];
    float a2 = f.x * sw[(j + 0) * 3 + 2] + f.y * sw[(j + 1) * 3 + 2] + f.z * sw[(j + 2) * 3 + 2] + f.w * sw[(j + 3) * 3 + 2];
    #pragma unroll
    for (int off = 16; off > 0; off >>= 1) {
        a0 += __shfl_down_sync(0xffffffffu, a0, off);
        a1 += __shfl_down_sync(0xffffffffu, a1, off);
        a2 += __shfl_down_sync(0xffffffffu, a2, off);
    }
    if (lane == 0) {
        float vx = verts[3 * w], vy = verts[3 * w + 1], vz = verts[3 * w + 2];
        a0 += vx * sw[(HID + 0) * 3 + 0] + vy * sw[(HID + 1) * 3 + 0] + vz * sw[(HID + 2) * 3 + 0] + ob[0];
        a1 += vx * sw[(HID + 0) * 3 + 1] + vy * sw[(HID + 1) * 3 + 1] + vz * sw[(HID + 2) * 3 + 1] + ob[1];
        a2 += vx * sw[(HID + 0) * 3 + 2] + vy * sw[(HID + 1) * 3 + 2] + vz * sw[(HID + 2) * 3 + 2] + ob[2];
        out[3 * w + 0] = vx + tanhf(a0);
        out[3 * w + 1] = vy + tanhf(a1);
        out[3 * w + 2] = vz + tanhf(a2);
    }
}

// ---------------- launch ----------------
extern "C" void kernel_launch(void* const* d_in, const int* in_sizes, int n_in,
                              void* d_out, int out_size) {
    const float* x     = (const float*)d_in[0];
    const float* verts = (const float*)d_in[1];
    const int*   edges = (const int*)  d_in[2];
    const float* bw    = (const float*)d_in[3];
    const float* bb    = (const float*)d_in[4];
    const float* w0    = (const float*)d_in[5];
    const float* b0    = (const float*)d_in[6];
    const float* w1    = (const float*)d_in[7];
    const float* b1    = (const float*)d_in[8];
    const float* ow    = (const float*)d_in[9];
    const float* ob    = (const float*)d_in[10];
    float* out = (float*)d_out;

    float *bufA, *bufB, *bufZ;
    cudaGetSymbolAddress((void**)&bufA, g_bufA);
    cudaGetSymbolAddress((void**)&bufB, g_bufB);
    cudaGetSymbolAddress((void**)&bufZ, g_bufZ);

    pixel_proj_kernel<<<NPIX / 2, dim3(HID, 2)>>>(x, bw);
    sample_kernel<<<NV / 8, 256>>>(verts, bb);          // -> g_bufA (post-relu)

    float* cur = bufA;   // activations input (relu applied on load; idempotent)
    float* nxt = bufB;
    for (int i = 0; i < 3; i++) {
        gemm131_kernel<<<NV / 128, 256>>>(cur, verts, w0 + (size_t)i * DIN * HID, b0 + (size_t)i * HID, nxt);
        gemm131_kernel<<<NV / 128, 256>>>(cur, verts, w1 + (size_t)i * DIN * HID, b1 + (size_t)i * HID, bufZ);
        scatter_kernel<<<NE / 8, 256>>>(edges, bufZ, nxt);
        float* t = cur; cur = nxt; nxt = t;
    }
    // after 3 swaps, 'cur' holds the last pre-activation (y + nbr) buffer (= bufB)
    final_kernel<<<NV / 8, 256>>>(cur, verts, ow, ob, out);
}

// round 6
// speedup vs baseline: 1.5825x; 1.5825x over previous
#include <cuda_runtime.h>
#include <cuda_bf16.h>
#include <math.h>
#include <stdint.h>

#define NV   262144
#define NE   786432
#define CIMG 256
#define HID  128
#define HW   64
#define NPIX (HW*HW)
#define DIN  (HID+3)
#define BM   64
#define KP   136                 // padded K stride (bf16 elems) -> conflict-free frags
#define NBLK (NV/BM)             // 4096

// Scratch (allowed: __device__ globals, no allocation)
__device__ float g_P[NPIX * HID];                  // 2 MB
__device__ float g_bufA[(size_t)NV * HID];
__device__ float g_bufB[(size_t)NV * HID];
__device__ float g_bufZ[(size_t)NV * HID];
__device__ __nv_bfloat16 g_Bhi[6 * 16384];         // weights bf16 hi, [n][k] row-major
__device__ __nv_bfloat16 g_Blo[6 * 16384];         // weights bf16 lo

// ---------------- helpers ----------------
__device__ __forceinline__ void red4(float* p, float4 v) {
    asm volatile("red.global.add.v4.f32 [%0], {%1, %2, %3, %4};"
                 :: "l"(p), "f"(v.x), "f"(v.y), "f"(v.z), "f"(v.w) : "memory");
}
__device__ __forceinline__ void mma16816(float* c, const uint32_t* a, const uint32_t* b) {
    asm volatile(
        "mma.sync.aligned.m16n8k16.row.col.f32.bf16.bf16.f32 "
        "{%0,%1,%2,%3}, {%4,%5,%6,%7}, {%8,%9}, {%0,%1,%2,%3};"
        : "+f"(c[0]), "+f"(c[1]), "+f"(c[2]), "+f"(c[3])
        : "r"(a[0]), "r"(a[1]), "r"(a[2]), "r"(a[3]), "r"(b[0]), "r"(b[1]));
}
__device__ __forceinline__ uint32_t pack_bf2(__nv_bfloat16 a, __nv_bfloat16 b) {
    return (uint32_t)__bfloat16_as_ushort(a) | ((uint32_t)__bfloat16_as_ushort(b) << 16);
}

// ---------------- kernel 0: weights -> bf16 hi/lo, [n][k] row-major ----------------
__global__ void convw_kernel(const float* __restrict__ w0, const float* __restrict__ w1) {
    int idx = blockIdx.x * 256 + threadIdx.x;     // 6*16384 total
    int m = idx >> 14;
    int e = idx & 16383;
    int n = e & 127;       // output col (GEMM N)
    int k = e >> 7;        // input dim  (GEMM K)
    const float* W = (m < 3) ? (w0 + (size_t)m * DIN * HID) : (w1 + (size_t)(m - 3) * DIN * HID);
    float v = W[(size_t)k * HID + n];
    __nv_bfloat16 hi = __float2bfloat16(v);
    float lo = v - __bfloat162float(hi);
    g_Bhi[(size_t)m * 16384 + n * 128 + k] = hi;
    g_Blo[(size_t)m * 16384 + n * 128 + k] = __float2bfloat16(lo);
}

// ---------------- kernel 1: P[p][j] = sum_c x[c][p] * bw[c][j] ----------------
__global__ void pixel_proj_kernel(const float* __restrict__ x, const float* __restrict__ bw) {
    int j = threadIdx.x;
    int p = blockIdx.x * blockDim.y + threadIdx.y;
    const float* xp = x + p;
    const float* wp = bw + j;
    float acc = 0.f;
    #pragma unroll 8
    for (int c = 0; c < CIMG; c++)
        acc = fmaf(xp[(size_t)c * NPIX], wp[(size_t)c * HID], acc);
    g_P[(size_t)p * HID + j] = acc;
}

// ---------------- kernel 2: bilinear blend + bias + relu -> g_bufA ----------------
__global__ void sample_kernel(const float* __restrict__ verts, const float* __restrict__ bb) {
    int w    = (blockIdx.x * blockDim.x + threadIdx.x) >> 5;
    int lane = threadIdx.x & 31;
    if (w >= NV) return;
    float vx = verts[3 * w], vy = verts[3 * w + 1];
    float px = (vx + 1.f) * 0.5f * (HW - 1);
    float py = (vy + 1.f) * 0.5f * (HW - 1);
    float fx = floorf(px), fy = floorf(py);
    float wx = px - fx,    wy = py - fy;
    int x0 = (int)fx; x0 = min(max(x0, 0), HW - 1); int x1 = min(x0 + 1, HW - 1);
    int y0 = (int)fy; y0 = min(max(y0, 0), HW - 1); int y1 = min(y0 + 1, HW - 1);

    const float* P00 = g_P + (size_t)(y0 * HW + x0) * HID;
    const float* P01 = g_P + (size_t)(y0 * HW + x1) * HID;
    const float* P10 = g_P + (size_t)(y1 * HW + x0) * HID;
    const float* P11 = g_P + (size_t)(y1 * HW + x1) * HID;

    int j = lane * 4;
    float4 a = *(const float4*)(P00 + j);
    float4 b = *(const float4*)(P01 + j);
    float4 c = *(const float4*)(P10 + j);
    float4 d = *(const float4*)(P11 + j);
    float4 bias4 = *(const float4*)(bb + j);

    float4 h;
    h.x = (a.x * (1.f - wx) + b.x * wx) * (1.f - wy) + (c.x * (1.f - wx) + d.x * wx) * wy + bias4.x;
    h.y = (a.y * (1.f - wx) + b.y * wx) * (1.f - wy) + (c.y * (1.f - wx) + d.y * wx) * wy + bias4.y;
    h.z = (a.z * (1.f - wx) + b.z * wx) * (1.f - wy) + (c.z * (1.f - wx) + d.z * wx) * wy + bias4.z;
    h.w = (a.w * (1.f - wx) + b.w * wx) * (1.f - wy) + (c.w * (1.f - wx) + d.w * wx) * wy + bias4.w;
    h.x = fmaxf(h.x, 0.f); h.y = fmaxf(h.y, 0.f); h.z = fmaxf(h.z, 0.f); h.w = fmaxf(h.w, 0.f);
    *(float4*)(g_bufA + (size_t)w * HID + j) = h;
}

// ---------------- kernel 3: HMMA GEMM (bf16 hi/lo split, 3 terms) ----------------
// Out[V,128] = relu(A[V,128]) @ W[0:128] + verts @ W[128:131] + bias
#define GEMM_SMEM ((BM*KP*2 + 128*KP*2) * 2 + 512 * 4)   // 106496 B

__global__ void __launch_bounds__(256, 2)
gemm_mma_kernel(const float* __restrict__ A, const float* __restrict__ verts,
                const __nv_bfloat16* __restrict__ Bhi, const __nv_bfloat16* __restrict__ Blo,
                const float* __restrict__ Wm, const float* __restrict__ bias,
                float* __restrict__ Out) {
    extern __shared__ char smraw[];
    __nv_bfloat16* Ah = (__nv_bfloat16*)smraw;         // BM x KP
    __nv_bfloat16* Al = Ah + BM * KP;
    __nv_bfloat16* Bh = Al + BM * KP;                  // 128 x KP
    __nv_bfloat16* Bl = Bh + 128 * KP;
    float* epi = (float*)(Bl + 128 * KP);              // [0:128) w128 row, [128) w129, [256) w130, [384) bias

    const int tid = threadIdx.x, lane = tid & 31, wid = tid >> 5;

    // stage B hi/lo (uint4 = 8 bf16)
    {
        const uint4* gh = (const uint4*)Bhi;
        const uint4* gl = (const uint4*)Blo;
        #pragma unroll
        for (int i = tid; i < 2048; i += 256) {
            int n = i >> 4, kc = (i & 15) * 8;
            *(uint4*)&Bh[n * KP + kc] = gh[i];
            *(uint4*)&Bl[n * KP + kc] = gl[i];
        }
    }
    if (tid < 128) {
        epi[tid]       = Wm[(size_t)(HID + 0) * HID + tid];
        epi[128 + tid] = Wm[(size_t)(HID + 1) * HID + tid];
        epi[256 + tid] = Wm[(size_t)(HID + 2) * HID + tid];
        epi[384 + tid] = bias[tid];
    }
    // stage A tile: relu + hi/lo split
    {
        const float* Asrc = A + (size_t)blockIdx.x * BM * HID;
        #pragma unroll
        for (int i = tid; i < BM * HID / 4; i += 256) {   // 2048 float4
            int r = i >> 5, c = (i & 31) * 4;
            float4 v = *(const float4*)(Asrc + (size_t)r * HID + c);
            v.x = fmaxf(v.x, 0.f); v.y = fmaxf(v.y, 0.f);
            v.z = fmaxf(v.z, 0.f); v.w = fmaxf(v.w, 0.f);
            __nv_bfloat16 hx = __float2bfloat16(v.x), hy = __float2bfloat16(v.y);
            __nv_bfloat16 hz = __float2bfloat16(v.z), hw = __float2bfloat16(v.w);
            uint2 hp, lp;
            hp.x = pack_bf2(hx, hy);
            hp.y = pack_bf2(hz, hw);
            lp.x = pack_bf2(__float2bfloat16(v.x - __bfloat162float(hx)),
                            __float2bfloat16(v.y - __bfloat162float(hy)));
            lp.y = pack_bf2(__float2bfloat16(v.z - __bfloat162float(hz)),
                            __float2bfloat16(v.w - __bfloat162float(hw)));
            *(uint2*)&Ah[r * KP + c] = hp;
            *(uint2*)&Al[r * KP + c] = lp;
        }
    }
    __syncthreads();

    const int m0 = (wid & 1) * 32;     // warp m-offset within tile
    const int n0 = (wid >> 1) * 32;    // warp n-offset
    const int g = lane >> 2, tig = lane & 3;

    float acc[2][4][4];
    #pragma unroll
    for (int i = 0; i < 2; i++)
        #pragma unroll
        for (int j = 0; j < 4; j++)
            #pragma unroll
            for (int q = 0; q < 4; q++) acc[i][j][q] = 0.f;

    #pragma unroll
    for (int kb = 0; kb < 8; kb++) {
        const int kof = kb * 16 + 2 * tig;
        uint32_t aH[2][4], aL[2][4], bH[4][2], bL[4][2];
        #pragma unroll
        for (int i = 0; i < 2; i++) {
            int r = m0 + i * 16 + g;
            const __nv_bfloat16* p0 = &Ah[r * KP + kof];
            const __nv_bfloat16* p1 = &Ah[(r + 8) * KP + kof];
            aH[i][0] = *(const uint32_t*)p0;       aH[i][1] = *(const uint32_t*)p1;
            aH[i][2] = *(const uint32_t*)(p0 + 8); aH[i][3] = *(const uint32_t*)(p1 + 8);
            const __nv_bfloat16* q0 = &Al[r * KP + kof];
            const __nv_bfloat16* q1 = &Al[(r + 8) * KP + kof];
            aL[i][0] = *(const uint32_t*)q0;       aL[i][1] = *(const uint32_t*)q1;
            aL[i][2] = *(const uint32_t*)(q0 + 8); aL[i][3] = *(const uint32_t*)(q1 + 8);
        }
        #pragma unroll
        for (int j = 0; j < 4; j++) {
            int n = n0 + j * 8 + g;
            const __nv_bfloat16* p = &Bh[n * KP + kof];
            bH[j][0] = *(const uint32_t*)p; bH[j][1] = *(const uint32_t*)(p + 8);
            const __nv_bfloat16* q = &Bl[n * KP + kof];
            bL[j][0] = *(const uint32_t*)q; bL[j][1] = *(const uint32_t*)(q + 8);
        }
        #pragma unroll
        for (int i = 0; i < 2; i++)
            #pragma unroll
            for (int j = 0; j < 4; j++) {
                mma16816(acc[i][j], aH[i], bH[j]);
                mma16816(acc[i][j], aH[i], bL[j]);
                mma16816(acc[i][j], aL[i], bH[j]);
            }
    }

    // epilogue: rank-3 verts update + bias
    #pragma unroll
    for (int i = 0; i < 2; i++) {
        int r0 = blockIdx.x * BM + m0 + i * 16 + g;
        int r1 = r0 + 8;
        float vx0 = verts[3 * r0], vy0 = verts[3 * r0 + 1], vz0 = verts[3 * r0 + 2];
        float vx1 = verts[3 * r1], vy1 = verts[3 * r1 + 1], vz1 = verts[3 * r1 + 2];
        #pragma unroll
        for (int j = 0; j < 4; j++) {
            int c = n0 + j * 8 + 2 * tig;
            float w0a = epi[c],       w0b = epi[c + 1];
            float w1a = epi[128 + c], w1b = epi[128 + c + 1];
            float w2a = epi[256 + c], w2b = epi[256 + c + 1];
            float ba  = epi[384 + c], bb2 = epi[384 + c + 1];
            float2 o01, o23;
            o01.x = acc[i][j][0] + vx0 * w0a + vy0 * w1a + vz0 * w2a + ba;
            o01.y = acc[i][j][1] + vx0 * w0b + vy0 * w1b + vz0 * w2b + bb2;
            o23.x = acc[i][j][2] + vx1 * w0a + vy1 * w1a + vz1 * w2a + ba;
            o23.y = acc[i][j][3] + vx1 * w0b + vy1 * w1b + vz1 * w2b + bb2;
            *(float2*)(Out + (size_t)r0 * HID + c) = o01;
            *(float2*)(Out + (size_t)r1 * HID + c) = o23;
        }
    }
}

// ---------------- kernel 4: edge scatter ----------------
__global__ void scatter_kernel(const int* __restrict__ edges,
                               const float* __restrict__ Z, float* __restrict__ Y) {
    int t = blockIdx.x * blockDim.x + threadIdx.x;
    int e = t >> 5;
    int lane = t & 31;
    if (e >= NE) return;
    int a = edges[2 * e], b = edges[2 * e + 1];
    int j = lane * 4;
    float4 zb = *(const float4*)(Z + (size_t)b * HID + j);
    red4(Y + (size_t)a * HID + j, zb);
    float4 za = *(const float4*)(Z + (size_t)a * HID + j);
    red4(Y + (size_t)b * HID + j, za);
}

// ---------------- kernel 5: final head ----------------
__global__ void final_kernel(const float* __restrict__ buf, const float* __restrict__ verts,
                             const float* __restrict__ ow, const float* __restrict__ ob,
                             float* __restrict__ out) {
    __shared__ float sw[DIN * 3];
    for (int i = threadIdx.x; i < DIN * 3; i += blockDim.x) sw[i] = ow[i];
    __syncthreads();

    int w    = (blockIdx.x * blockDim.x + threadIdx.x) >> 5;
    int lane = threadIdx.x & 31;
    if (w >= NV) return;
    int j = lane * 4;
    float4 f = *(const float4*)(buf + (size_t)w * HID + j);
    f.x = fmaxf(f.x, 0.f); f.y = fmaxf(f.y, 0.f); f.z = fmaxf(f.z, 0.f); f.w = fmaxf(f.w, 0.f);
    *(float4*)(out + (size_t)3 * NV + (size_t)w * HID + j) = f;

    float a0 = f.x * sw[(j + 0) * 3 + 0] + f.y * sw[(j + 1) * 3 + 0] + f.z * sw[(j + 2) * 3 + 0] + f.w * sw[(j + 3) * 3 + 0];
    float a1 = f.x * sw[(j + 0) * 3 + 1] + f.y * sw[(j + 1) * 3 + 1] + f.z * sw[(j + 2) * 3 + 1] + f.w * sw[(j + 3) * 3 + 1];
    float a2 = f.x * sw[(j + 0) * 3 + 2] + f.y * sw[(j + 1) * 3 + 2] + f.z * sw[(j + 2) * 3 + 2] + f.w * sw[(j + 3) * 3 + 2];
    #pragma unroll
    for (int off = 16; off > 0; off >>= 1) {
        a0 += __shfl_down_sync(0xffffffffu, a0, off);
        a1 += __shfl_down_sync(0xffffffffu, a1, off);
        a2 += __shfl_down_sync(0xffffffffu, a2, off);
    }
    if (lane == 0) {
        float vx = verts[3 * w], vy = verts[3 * w + 1], vz = verts[3 * w + 2];
        a0 += vx * sw[(HID + 0) * 3 + 0] + vy * sw[(HID + 1) * 3 + 0] + vz * sw[(HID + 2) * 3 + 0] + ob[0];
        a1 += vx * sw[(HID + 0) * 3 + 1] + vy * sw[(HID + 1) * 3 + 1] + vz * sw[(HID + 2) * 3 + 1] + ob[1];
        a2 += vx * sw[(HID + 0) * 3 + 2] + vy * sw[(HID + 1) * 3 + 2] + vz * sw[(HID + 2) * 3 + 2] + ob[2];
        out[3 * w + 0] = vx + tanhf(a0);
        out[3 * w + 1] = vy + tanhf(a1);
        out[3 * w + 2] = vz + tanhf(a2);
    }
}

// ---------------- launch ----------------
extern "C" void kernel_launch(void* const* d_in, const int* in_sizes, int n_in,
                              void* d_out, int out_size) {
    const float* x     = (const float*)d_in[0];
    const float* verts = (const float*)d_in[1];
    const int*   edges = (const int*)  d_in[2];
    const float* bw    = (const float*)d_in[3];
    const float* bb    = (const float*)d_in[4];
    const float* w0    = (const float*)d_in[5];
    const float* b0    = (const float*)d_in[6];
    const float* w1    = (const float*)d_in[7];
    const float* b1    = (const float*)d_in[8];
    const float* ow    = (const float*)d_in[9];
    const float* ob    = (const float*)d_in[10];
    float* out = (float*)d_out;

    float *bufA, *bufB, *bufZ;
    __nv_bfloat16 *Bhi, *Blo;
    cudaGetSymbolAddress((void**)&bufA, g_bufA);
    cudaGetSymbolAddress((void**)&bufB, g_bufB);
    cudaGetSymbolAddress((void**)&bufZ, g_bufZ);
    cudaGetSymbolAddress((void**)&Bhi, g_Bhi);
    cudaGetSymbolAddress((void**)&Blo, g_Blo);

    cudaFuncSetAttribute(gemm_mma_kernel, cudaFuncAttributeMaxDynamicSharedMemorySize, GEMM_SMEM);

    convw_kernel<<<6 * 16384 / 256, 256>>>(w0, w1);
    pixel_proj_kernel<<<NPIX / 2, dim3(HID, 2)>>>(x, bw);
    sample_kernel<<<NV / 8, 256>>>(verts, bb);          // -> g_bufA (post-relu)

    float* cur = bufA;   // relu applied on GEMM load (idempotent for bufA)
    float* nxt = bufB;
    for (int i = 0; i < 3; i++) {
        gemm_mma_kernel<<<NBLK, 256, GEMM_SMEM>>>(
            cur, verts, Bhi + (size_t)i * 16384, Blo + (size_t)i * 16384,
            w0 + (size_t)i * DIN * HID, b0 + (size_t)i * HID, nxt);
        gemm_mma_kernel<<<NBLK, 256, GEMM_SMEM>>>(
            cur, verts, Bhi + (size_t)(3 + i) * 16384, Blo + (size_t)(3 + i) * 16384,
            w1 + (size_t)i * DIN * HID, b1 + (size_t)i * HID, bufZ);
        scatter_kernel<<<NE / 8, 256>>>(edges, bufZ, nxt);
        float* t = cur; cur = nxt; nxt = t;
    }
    final_kernel<<<NV / 8, 256>>>(cur, verts, ow, ob, out);
}

// round 8
// speedup vs baseline: 2.2478x; 1.4204x over previous
#include <cuda_runtime.h>
#include <cuda_bf16.h>
#include <math.h>
#include <stdint.h>

#define NV   262144
#define NE   786432
#define CIMG 256
#define HID  128
#define HW   64
#define NPIX (HW*HW)
#define DIN  (HID+3)
#define BM   64
#define KP   136                 // padded K stride (bf16 elems) -> conflict-free frags
#define NBLK (NV/BM)             // 4096
#define DEGCAP 32

// Scratch (allowed: __device__ globals, no allocation)
__device__ float g_P[NPIX * HID];                  // 2 MB, L2-resident
__device__ float g_bufA[(size_t)NV * HID];
__device__ float g_bufB[(size_t)NV * HID];
__device__ float g_bufZ[(size_t)NV * HID];
__device__ __nv_bfloat16 g_Bhi[6 * 16384];         // weights bf16 hi, [n][k] row-major
__device__ __nv_bfloat16 g_Blo[6 * 16384];         // weights bf16 lo
__device__ int g_cnt[NV];                          // 1 MB
__device__ int g_adj[(size_t)NV * DEGCAP];         // 33.5 MB

// ---------------- helpers ----------------
__device__ __forceinline__ void mma16816(float* c, const uint32_t* a, const uint32_t* b) {
    asm volatile(
        "mma.sync.aligned.m16n8k16.row.col.f32.bf16.bf16.f32 "
        "{%0,%1,%2,%3}, {%4,%5,%6,%7}, {%8,%9}, {%0,%1,%2,%3};"
        : "+f"(c[0]), "+f"(c[1]), "+f"(c[2]), "+f"(c[3])
        : "r"(a[0]), "r"(a[1]), "r"(a[2]), "r"(a[3]), "r"(b[0]), "r"(b[1]));
}
__device__ __forceinline__ uint32_t pack_bf2(__nv_bfloat16 a, __nv_bfloat16 b) {
    return (uint32_t)__bfloat16_as_ushort(a) | ((uint32_t)__bfloat16_as_ushort(b) << 16);
}

// ---------------- kernel 0: weights -> bf16 hi/lo, [n][k] row-major ----------------
__global__ void convw_kernel(const float* __restrict__ w0, const float* __restrict__ w1) {
    int idx = blockIdx.x * 256 + threadIdx.x;     // 6*16384 total
    int m = idx >> 14;
    int e = idx & 16383;
    int n = e & 127;       // output col (GEMM N)
    int k = e >> 7;        // input dim  (GEMM K)
    const float* W = (m < 3) ? (w0 + (size_t)m * DIN * HID) : (w1 + (size_t)(m - 3) * DIN * HID);
    float v = W[(size_t)k * HID + n];
    __nv_bfloat16 hi = __float2bfloat16(v);
    float lo = v - __bfloat162float(hi);
    g_Bhi[(size_t)m * 16384 + n * 128 + k] = hi;
    g_Blo[(size_t)m * 16384 + n * 128 + k] = __float2bfloat16(lo);
}

// ---------------- kernel 1: P[p][j] = sum_c x[c][p] * bw[c][j] ----------------
__global__ void pixel_proj_kernel(const float* __restrict__ x, const float* __restrict__ bw) {
    int j = threadIdx.x;
    int p = blockIdx.x * blockDim.y + threadIdx.y;
    const float* xp = x + p;
    const float* wp = bw + j;
    float acc = 0.f;
    #pragma unroll 8
    for (int c = 0; c < CIMG; c++)
        acc = fmaf(xp[(size_t)c * NPIX], wp[(size_t)c * HID], acc);
    g_P[(size_t)p * HID + j] = acc;
}

// ---------------- adjacency build ----------------
__global__ void zero_cnt_kernel() {
    int v = blockIdx.x * 1024 + threadIdx.x;
    if (v < NV) g_cnt[v] = 0;
}
__global__ void fill_adj_kernel(const int* __restrict__ edges) {
    int e = blockIdx.x * 256 + threadIdx.x;
    if (e >= NE) return;
    int a = edges[2 * e], b = edges[2 * e + 1];
    int sa = atomicAdd(&g_cnt[a], 1);
    if (sa < DEGCAP) g_adj[(size_t)a * DEGCAP + sa] = b;
    int sb = atomicAdd(&g_cnt[b], 1);
    if (sb < DEGCAP) g_adj[(size_t)b * DEGCAP + sb] = a;
}

// ---------------- gather: Y[v] += sum_nbr Z[nbr]  (in-place on Y) ----------------
__global__ void gather_kernel(const float* __restrict__ Z, float* __restrict__ Y) {
    int v    = (blockIdx.x * blockDim.x + threadIdx.x) >> 5;
    int lane = threadIdx.x & 31;
    if (v >= NV) return;
    int cnt = min(g_cnt[v], DEGCAP);
    int u = (lane < cnt) ? g_adj[(size_t)v * DEGCAP + lane] : 0;
    float4 acc = *(const float4*)(Y + (size_t)v * HID + lane * 4);
    int i = 0;
    for (; i + 2 <= cnt; i += 2) {
        int u0 = __shfl_sync(0xffffffffu, u, i);
        int u1 = __shfl_sync(0xffffffffu, u, i + 1);
        float4 z0 = *(const float4*)(Z + (size_t)u0 * HID + lane * 4);
        float4 z1 = *(const float4*)(Z + (size_t)u1 * HID + lane * 4);
        acc.x += z0.x + z1.x; acc.y += z0.y + z1.y;
        acc.z += z0.z + z1.z; acc.w += z0.w + z1.w;
    }
    if (i < cnt) {
        int u0 = __shfl_sync(0xffffffffu, u, i);
        float4 z0 = *(const float4*)(Z + (size_t)u0 * HID + lane * 4);
        acc.x += z0.x; acc.y += z0.y; acc.z += z0.z; acc.w += z0.w;
    }
    *(float4*)(Y + (size_t)v * HID + lane * 4) = acc;
}

// ---------------- gather + final head fused (layer 3) ----------------
// row = y3[v] + sum Z[nbr]; feats = relu(row) -> out[3V + ...];
// out[3v..] = verts + tanh(concat(feats,verts) @ ow + ob)
__global__ void gather_final_kernel(const float* __restrict__ Z, const float* __restrict__ Ybuf,
                                    const float* __restrict__ verts,
                                    const float* __restrict__ ow, const float* __restrict__ ob,
                                    float* __restrict__ out) {
    __shared__ float sw[DIN * 3];
    for (int i = threadIdx.x; i < DIN * 3; i += blockDim.x) sw[i] = ow[i];
    __syncthreads();

    int v    = (blockIdx.x * blockDim.x + threadIdx.x) >> 5;
    int lane = threadIdx.x & 31;
    if (v >= NV) return;
    int cnt = min(g_cnt[v], DEGCAP);
    int u = (lane < cnt) ? g_adj[(size_t)v * DEGCAP + lane] : 0;
    float4 acc = *(const float4*)(Ybuf + (size_t)v * HID + lane * 4);
    int i = 0;
    for (; i + 2 <= cnt; i += 2) {
        int u0 = __shfl_sync(0xffffffffu, u, i);
        int u1 = __shfl_sync(0xffffffffu, u, i + 1);
        float4 z0 = *(const float4*)(Z + (size_t)u0 * HID + lane * 4);
        float4 z1 = *(const float4*)(Z + (size_t)u1 * HID + lane * 4);
        acc.x += z0.x + z1.x; acc.y += z0.y + z1.y;
        acc.z += z0.z + z1.z; acc.w += z0.w + z1.w;
    }
    if (i < cnt) {
        int u0 = __shfl_sync(0xffffffffu, u, i);
        float4 z0 = *(const float4*)(Z + (size_t)u0 * HID + lane * 4);
        acc.x += z0.x; acc.y += z0.y; acc.z += z0.z; acc.w += z0.w;
    }

    float4 f;
    f.x = fmaxf(acc.x, 0.f); f.y = fmaxf(acc.y, 0.f);
    f.z = fmaxf(acc.z, 0.f); f.w = fmaxf(acc.w, 0.f);
    int j = lane * 4;
    *(float4*)(out + (size_t)3 * NV + (size_t)v * HID + j) = f;

    float a0 = f.x * sw[(j + 0) * 3 + 0] + f.y * sw[(j + 1) * 3 + 0] + f.z * sw[(j + 2) * 3 + 0] + f.w * sw[(j + 3) * 3 + 0];
    float a1 = f.x * sw[(j + 0) * 3 + 1] + f.y * sw[(j + 1) * 3 + 1] + f.z * sw[(j + 2) * 3 + 1] + f.w * sw[(j + 3) * 3 + 1];
    float a2 = f.x * sw[(j + 0) * 3 + 2] + f.y * sw[(j + 1) * 3 + 2] + f.z * sw[(j + 2) * 3 + 2] + f.w * sw[(j + 3) * 3 + 2];
    #pragma unroll
    for (int off = 16; off > 0; off >>= 1) {
        a0 += __shfl_down_sync(0xffffffffu, a0, off);
        a1 += __shfl_down_sync(0xffffffffu, a1, off);
        a2 += __shfl_down_sync(0xffffffffu, a2, off);
    }
    if (lane == 0) {
        float vx = verts[3 * v], vy = verts[3 * v + 1], vz = verts[3 * v + 2];
        a0 += vx * sw[(HID + 0) * 3 + 0] + vy * sw[(HID + 1) * 3 + 0] + vz * sw[(HID + 2) * 3 + 0] + ob[0];
        a1 += vx * sw[(HID + 0) * 3 + 1] + vy * sw[(HID + 1) * 3 + 1] + vz * sw[(HID + 2) * 3 + 1] + ob[1];
        a2 += vx * sw[(HID + 0) * 3 + 2] + vy * sw[(HID + 1) * 3 + 2] + vz * sw[(HID + 2) * 3 + 2] + ob[2];
        out[3 * v + 0] = vx + tanhf(a0);
        out[3 * v + 1] = vy + tanhf(a1);
        out[3 * v + 2] = vz + tanhf(a2);
    }
}

// ---------------- kernel 3: HMMA GEMM (bf16 hi/lo split, 3 terms) ----------------
// sample_mode=0: A-tile = relu(A[V,128])
// sample_mode=1: A-tile = relu(bilinear(g_P, verts) + bbias)   (layer-1 fusion)
// Out = Atile @ W[0:128] + verts @ W[128:131] + bias
#define GEMM_SMEM ((BM*KP*2 + 128*KP*2) * 2 + 512 * 4)   // 106496 B

__global__ void __launch_bounds__(256, 2)
gemm_mma_kernel(const float* __restrict__ A, const float* __restrict__ verts,
                const __nv_bfloat16* __restrict__ Bhi, const __nv_bfloat16* __restrict__ Blo,
                const float* __restrict__ Wm, const float* __restrict__ bias,
                float* __restrict__ Out, int sample_mode, const float* __restrict__ bbias) {
    extern __shared__ char smraw[];
    __nv_bfloat16* Ah = (__nv_bfloat16*)smraw;         // BM x KP
    __nv_bfloat16* Al = Ah + BM * KP;
    __nv_bfloat16* Bh = Al + BM * KP;                  // 128 x KP
    __nv_bfloat16* Bl = Bh + 128 * KP;
    float* epi = (float*)(Bl + 128 * KP);              // w128,w129,w130,bias rows

    const int tid = threadIdx.x, lane = tid & 31, wid = tid >> 5;

    // stage B hi/lo (uint4 = 8 bf16)
    {
        const uint4* gh = (const uint4*)Bhi;
        const uint4* gl = (const uint4*)Blo;
        #pragma unroll
        for (int i = tid; i < 2048; i += 256) {
            int n = i >> 4, kc = (i & 15) * 8;
            *(uint4*)&Bh[n * KP + kc] = gh[i];
            *(uint4*)&Bl[n * KP + kc] = gl[i];
        }
    }
    if (tid < 128) {
        epi[tid]       = Wm[(size_t)(HID + 0) * HID + tid];
        epi[128 + tid] = Wm[(size_t)(HID + 1) * HID + tid];
        epi[256 + tid] = Wm[(size_t)(HID + 2) * HID + tid];
        epi[384 + tid] = bias[tid];
    }
    // stage A tile: relu + hi/lo split
    if (!sample_mode) {
        const float* Asrc = A + (size_t)blockIdx.x * BM * HID;
        #pragma unroll
        for (int i = tid; i < BM * HID / 4; i += 256) {   // 2048 float4
            int r = i >> 5, c = (i & 31) * 4;
            float4 v = *(const float4*)(Asrc + (size_t)r * HID + c);
            v.x = fmaxf(v.x, 0.f); v.y = fmaxf(v.y, 0.f);
            v.z = fmaxf(v.z, 0.f); v.w = fmaxf(v.w, 0.f);
            __nv_bfloat16 hx = __float2bfloat16(v.x), hy = __float2bfloat16(v.y);
            __nv_bfloat16 hz = __float2bfloat16(v.z), hw = __float2bfloat16(v.w);
            uint2 hp, lp;
            hp.x = pack_bf2(hx, hy);
            hp.y = pack_bf2(hz, hw);
            lp.x = pack_bf2(__float2bfloat16(v.x - __bfloat162float(hx)),
                            __float2bfloat16(v.y - __bfloat162float(hy)));
            lp.y = pack_bf2(__float2bfloat16(v.z - __bfloat162float(hz)),
                            __float2bfloat16(v.w - __bfloat162float(hw)));
            *(uint2*)&Ah[r * KP + c] = hp;
            *(uint2*)&Al[r * KP + c] = lp;
        }
    } else {
        // fused bilinear sampling from L2-resident g_P
        #pragma unroll
        for (int i = tid; i < BM * HID / 4; i += 256) {
            int r = i >> 5, c = (i & 31) * 4;
            int vtx = blockIdx.x * BM + r;
            float vx = verts[3 * vtx], vy = verts[3 * vtx + 1];
            float px = (vx + 1.f) * 0.5f * (HW - 1);
            float py = (vy + 1.f) * 0.5f * (HW - 1);
            float fx = floorf(px), fy = floorf(py);
            float wx = px - fx,    wy = py - fy;
            int x0 = (int)fx; x0 = min(max(x0, 0), HW - 1); int x1 = min(x0 + 1, HW - 1);
            int y0 = (int)fy; y0 = min(max(y0, 0), HW - 1); int y1 = min(y0 + 1, HW - 1);
            const float* P00 = g_P + (size_t)(y0 * HW + x0) * HID;
            const float* P01 = g_P + (size_t)(y0 * HW + x1) * HID;
            const float* P10 = g_P + (size_t)(y1 * HW + x0) * HID;
            const float* P11 = g_P + (size_t)(y1 * HW + x1) * HID;
            float4 a = *(const float4*)(P00 + c);
            float4 b = *(const float4*)(P01 + c);
            float4 cc = *(const float4*)(P10 + c);
            float4 d = *(const float4*)(P11 + c);
            float4 b4 = *(const float4*)(bbias + c);
            float4 v;
            v.x = (a.x * (1.f - wx) + b.x * wx) * (1.f - wy) + (cc.x * (1.f - wx) + d.x * wx) * wy + b4.x;
            v.y = (a.y * (1.f - wx) + b.y * wx) * (1.f - wy) + (cc.y * (1.f - wx) + d.y * wx) * wy + b4.y;
            v.z = (a.z * (1.f - wx) + b.z * wx) * (1.f - wy) + (cc.z * (1.f - wx) + d.z * wx) * wy + b4.z;
            v.w = (a.w * (1.f - wx) + b.w * wx) * (1.f - wy) + (cc.w * (1.f - wx) + d.w * wx) * wy + b4.w;
            v.x = fmaxf(v.x, 0.f); v.y = fmaxf(v.y, 0.f);
            v.z = fmaxf(v.z, 0.f); v.w = fmaxf(v.w, 0.f);
            __nv_bfloat16 hx = __float2bfloat16(v.x), hy = __float2bfloat16(v.y);
            __nv_bfloat16 hz = __float2bfloat16(v.z), hw = __float2bfloat16(v.w);
            uint2 hp, lp;
            hp.x = pack_bf2(hx, hy);
            hp.y = pack_bf2(hz, hw);
            lp.x = pack_bf2(__float2bfloat16(v.x - __bfloat162float(hx)),
                            __float2bfloat16(v.y - __bfloat162float(hy)));
            lp.y = pack_bf2(__float2bfloat16(v.z - __bfloat162float(hz)),
                            __float2bfloat16(v.w - __bfloat162float(hw)));
            *(uint2*)&Ah[r * KP + c] = hp;
            *(uint2*)&Al[r * KP + c] = lp;
        }
    }
    __syncthreads();

    const int m0 = (wid & 1) * 32;     // warp m-offset within tile
    const int n0 = (wid >> 1) * 32;    // warp n-offset
    const int g = lane >> 2, tig = lane & 3;

    float acc[2][4][4];
    #pragma unroll
    for (int i = 0; i < 2; i++)
        #pragma unroll
        for (int j = 0; j < 4; j++)
            #pragma unroll
            for (int q = 0; q < 4; q++) acc[i][j][q] = 0.f;

    #pragma unroll
    for (int kb = 0; kb < 8; kb++) {
        const int kof = kb * 16 + 2 * tig;
        uint32_t aH[2][4], aL[2][4], bH[4][2], bL[4][2];
        #pragma unroll
        for (int i = 0; i < 2; i++) {
            int r = m0 + i * 16 + g;
            const __nv_bfloat16* p0 = &Ah[r * KP + kof];
            const __nv_bfloat16* p1 = &Ah[(r + 8) * KP + kof];
            aH[i][0] = *(const uint32_t*)p0;       aH[i][1] = *(const uint32_t*)p1;
            aH[i][2] = *(const uint32_t*)(p0 + 8); aH[i][3] = *(const uint32_t*)(p1 + 8);
            const __nv_bfloat16* q0 = &Al[r * KP + kof];
            const __nv_bfloat16* q1 = &Al[(r + 8) * KP + kof];
            aL[i][0] = *(const uint32_t*)q0;       aL[i][1] = *(const uint32_t*)q1;
            aL[i][2] = *(const uint32_t*)(q0 + 8); aL[i][3] = *(const uint32_t*)(q1 + 8);
        }
        #pragma unroll
        for (int j = 0; j < 4; j++) {
            int n = n0 + j * 8 + g;
            const __nv_bfloat16* p = &Bh[n * KP + kof];
            bH[j][0] = *(const uint32_t*)p; bH[j][1] = *(const uint32_t*)(p + 8);
            const __nv_bfloat16* q = &Bl[n * KP + kof];
            bL[j][0] = *(const uint32_t*)q; bL[j][1] = *(const uint32_t*)(q + 8);
        }
        #pragma unroll
        for (int i = 0; i < 2; i++)
            #pragma unroll
            for (int j = 0; j < 4; j++) {
                mma16816(acc[i][j], aH[i], bH[j]);
                mma16816(acc[i][j], aH[i], bL[j]);
                mma16816(acc[i][j], aL[i], bH[j]);
            }
    }

    // epilogue: rank-3 verts update + bias
    #pragma unroll
    for (int i = 0; i < 2; i++) {
        int r0 = blockIdx.x * BM + m0 + i * 16 + g;
        int r1 = r0 + 8;
        float vx0 = verts[3 * r0], vy0 = verts[3 * r0 + 1], vz0 = verts[3 * r0 + 2];
        float vx1 = verts[3 * r1], vy1 = verts[3 * r1 + 1], vz1 = verts[3 * r1 + 2];
        #pragma unroll
        for (int j = 0; j < 4; j++) {
            int c = n0 + j * 8 + 2 * tig;
            float w0a = epi[c],       w0b = epi[c + 1];
            float w1a = epi[128 + c], w1b = epi[128 + c + 1];
            float w2a = epi[256 + c], w2b = epi[256 + c + 1];
            float ba  = epi[384 + c], bb2 = epi[384 + c + 1];
            float2 o01, o23;
            o01.x = acc[i][j][0] + vx0 * w0a + vy0 * w1a + vz0 * w2a + ba;
            o01.y = acc[i][j][1] + vx0 * w0b + vy0 * w1b + vz0 * w2b + bb2;
            o23.x = acc[i][j][2] + vx1 * w0a + vy1 * w1a + vz1 * w2a + ba;
            o23.y = acc[i][j][3] + vx1 * w0b + vy1 * w1b + vz1 * w2b + bb2;
            *(float2*)(Out + (size_t)r0 * HID + c) = o01;
            *(float2*)(Out + (size_t)r1 * HID + c) = o23;
        }
    }
}

// ---------------- launch ----------------
extern "C" void kernel_launch(void* const* d_in, const int* in_sizes, int n_in,
                              void* d_out, int out_size) {
    const float* x     = (const float*)d_in[0];
    const float* verts = (const float*)d_in[1];
    const int*   edges = (const int*)  d_in[2];
    const float* bw    = (const float*)d_in[3];
    const float* bb    = (const float*)d_in[4];
    const float* w0    = (const float*)d_in[5];
    const float* b0    = (const float*)d_in[6];
    const float* w1    = (const float*)d_in[7];
    const float* b1    = (const float*)d_in[8];
    const float* ow    = (const float*)d_in[9];
    const float* ob    = (const float*)d_in[10];
    float* out = (float*)d_out;

    float *bufA, *bufB, *bufZ;
    __nv_bfloat16 *Bhi, *Blo;
    cudaGetSymbolAddress((void**)&bufA, g_bufA);
    cudaGetSymbolAddress((void**)&bufB, g_bufB);
    cudaGetSymbolAddress((void**)&bufZ, g_bufZ);
    cudaGetSymbolAddress((void**)&Bhi, g_Bhi);
    cudaGetSymbolAddress((void**)&Blo, g_Blo);

    cudaFuncSetAttribute(gemm_mma_kernel, cudaFuncAttributeMaxDynamicSharedMemorySize, GEMM_SMEM);

    convw_kernel<<<6 * 16384 / 256, 256>>>(w0, w1);
    pixel_proj_kernel<<<NPIX / 2, dim3(HID, 2)>>>(x, bw);
    zero_cnt_kernel<<<NV / 1024, 1024>>>();
    fill_adj_kernel<<<NE / 256, 256>>>(edges);

    // layer 1 (A fused-sampled from g_P)
    gemm_mma_kernel<<<NBLK, 256, GEMM_SMEM>>>(nullptr, verts, Bhi, Blo,
                                              w0, b0, bufB, 1, bb);
    gemm_mma_kernel<<<NBLK, 256, GEMM_SMEM>>>(nullptr, verts, Bhi + 3 * 16384, Blo + 3 * 16384,
                                              w1, b1, bufZ, 1, bb);
    gather_kernel<<<NV / 8, 256>>>(bufZ, bufB);

    // layer 2
    gemm_mma_kernel<<<NBLK, 256, GEMM_SMEM>>>(bufB, verts, Bhi + 1 * 16384, Blo + 1 * 16384,
                                              w0 + (size_t)1 * DIN * HID, b0 + HID, bufA, 0, bb);
    gemm_mma_kernel<<<NBLK, 256, GEMM_SMEM>>>(bufB, verts, Bhi + 4 * 16384, Blo + 4 * 16384,
                                              w1 + (size_t)1 * DIN * HID, b1 + HID, bufZ, 0, bb);
    gather_kernel<<<NV / 8, 256>>>(bufZ, bufA);

    // layer 3 (gather fused with final head)
    gemm_mma_kernel<<<NBLK, 256, GEMM_SMEM>>>(bufA, verts, Bhi + 2 * 16384, Blo + 2 * 16384,
                                              w0 + (size_t)2 * DIN * HID, b0 + 2 * HID, bufB, 0, bb);
    gemm_mma_kernel<<<NBLK, 256, GEMM_SMEM>>>(bufA, verts, Bhi + 5 * 16384, Blo + 5 * 16384,
                                              w1 + (size_t)2 * DIN * HID, b1 + 2 * HID, bufZ, 0, bb);
    gather_final_kernel<<<NV / 8, 256>>>(bufZ, bufB, verts, ow, ob, out);
}